// round 6
// baseline (speedup 1.0000x reference)
#include <cuda_runtime.h>
#include <cuda_bf16.h>
#include <cstdint>

#define Hdim 64
#define Wdim 64
#define Bn   8
#define HIDc 32
#define Tn   16
#define CINx 16

#define CC   4          // input-channel chunk staged per buffer
#define TH   16         // y-rows per block (8 warps x 2 rows)
#define SSTR 68         // smem input row stride (64 + 2 halo + pad)

using ull = unsigned long long;

// Persistent cell state (device globals; NOT allocated, per harness rules).
__device__ float g_c0[(size_t)Bn * HIDc * Hdim * Wdim];
__device__ float g_c1[(size_t)Bn * HIDc * Hdim * Wdim];

__device__ __forceinline__ float sigm(float v) {
    return __fdividef(1.0f, 1.0f + __expf(-v));
}
__device__ __forceinline__ float tanh_fast(float v) {
    return 2.0f * sigm(2.0f * v) - 1.0f;
}

__device__ __forceinline__ void ffma2(ull& d, ull a, ull b) {
    asm("fma.rn.f32x2 %0, %1, %2, %0;" : "+l"(d) : "l"(a), "l"(b));
}
__device__ __forceinline__ ull pack2(float v) {
    ull r;
    asm("mov.b64 %0, {%1, %1};" : "=l"(r) : "f"(v));
    return r;
}
__device__ __forceinline__ float2 unpack2(ull v) {
    float2 f;
    asm("mov.b64 {%0, %1}, %2;" : "=f"(f.x), "=f"(f.y) : "l"(v));
    return f;
}

#define S_IN_CH   ((TH + 2) * SSTR)         // 18*68 = 1224 floats per channel
#define S_IN_BUF  (CC * S_IN_CH)            // 4896 floats per buffer
#define S_W_BUF   (CC * 9 * 8)              // 288 floats per buffer

// One ConvLSTM step for one layer.
// Grid: (Hdim/TH=4, Bn, 16 hidden-channel groups of 2). Block: 256 threads.
// Warp ty covers rows {2ty, 2ty+1}; lane l: sub-row l>>4, x0 = (l&15)*4.
// Each thread: 4 x-positions x (4 gates x 2 hidden channels), b64 accumulators.
// Chunk loop is ping-pong double-buffered: stage(c+1) overlaps compute(c),
// one __syncthreads per chunk.
template<int CIN_X, int LAYER>
__global__ __launch_bounds__(256, 4)
void step_kernel(const float* __restrict__ xsrc,   // [B, CIN_X, H, W]
                 const float* __restrict__ hsrc,   // [B, 32, H, W] (prev h) or null
                 const float* __restrict__ Wt,     // [128, CIN_X+32, 3, 3]
                 const float* __restrict__ bias,   // [128]
                 float* __restrict__ h_out,        // [B, 32, H, W]
                 int t0)
{
    constexpr int CIN_TOT = CIN_X + HIDc;            // 48 or 64
    constexpr int NCHUNK  = CIN_TOT / CC;            // 12 or 16
    __shared__ __align__(16) float s_in[2 * S_IN_BUF];   // 39168 B
    __shared__ __align__(16) float s_w[2 * S_W_BUF];     //  2304 B

    float* c_state = (LAYER == 0) ? g_c0 : g_c1;

    const int tid = threadIdx.x;
    const int l   = tid & 31;
    const int ty  = tid >> 5;
    const int sub = l >> 4;
    const int x0  = (l & 15) * 4;
    const int r   = ty * 2 + sub;        // row within tile, 0..15
    const int gy0 = blockIdx.x * TH;
    const int b   = blockIdx.y;
    const int hcg = blockIdx.z;          // hidden channels {2*hcg, 2*hcg+1}

    // Staging role: warp ty stages channel cl = ty>>1, row-half ty&1 (9 rows).
    const int st_cl  = ty >> 1;
    const int st_r0  = (ty & 1) * 9;

    ull acc[4][4];
#pragma unroll
    for (int xp = 0; xp < 4; xp++)
#pragma unroll
        for (int g = 0; g < 4; g++) acc[xp][g] = 0ull;

    // ---- staging helper (inlined twice: prologue + loop) ----
    auto stage = [&](int chunk, int buf) {
        // input: 4 channels x 18 rows, split 8 warps x 9 rows
        const int c = chunk * CC + st_cl;
        const float* base = nullptr;
        if (c < CIN_X)
            base = xsrc + (size_t)(b * CIN_X + c) * (Hdim * Wdim);
        else if (!t0)
            base = hsrc + (size_t)(b * HIDc + (c - CIN_X)) * (Hdim * Wdim);
        float* dst = &s_in[buf * S_IN_BUF + st_cl * S_IN_CH + st_r0 * SSTR];
#pragma unroll
        for (int j = 0; j < 9; j++) {
            const int rr = st_r0 + j;
            const int y  = gy0 - 1 + rr;
            const bool yok = (base != nullptr) & (y >= 0) & (y < Hdim);
            float v0 = 0.0f, v1 = 0.0f, v2 = 0.0f;
            if (yok) {
                const float* srow = base + (size_t)y * Wdim;
                if (l >= 1) v0 = srow[l - 1];
                v1 = srow[l + 31];
                if (l == 0) v2 = srow[63];
            }
            float* drow = dst + j * SSTR;
            drow[l] = v0;
            drow[l + 32] = v1;
            if (l < 2) drow[l + 64] = v2;
        }
        // weights: 288 floats, layout [ci][k][8 gch], gch = gate*2 + hci
#pragma unroll
        for (int it = 0; it < 2; it++) {
            const int idx = tid + it * 256;
            if (idx < S_W_BUF) {
                const int ci  = idx / 72;
                const int rem = idx - ci * 72;
                const int k   = rem >> 3;
                const int gi  = rem & 7;
                const int oc  = (gi >> 1) * HIDc + hcg * 2 + (gi & 1);
                s_w[buf * S_W_BUF + idx] =
                    Wt[((size_t)oc * CIN_TOT + (chunk * CC + ci)) * 9 + k];
            }
        }
    };

    auto compute = [&](int buf) {
        const float* sin_b = &s_in[buf * S_IN_BUF];
        const float* sw_b  = &s_w[buf * S_W_BUF];
#pragma unroll
        for (int ci = 0; ci < CC; ci++) {
#pragma unroll
            for (int ky = 0; ky < 3; ky++) {
                const float* rowp = &sin_b[(ci * (TH + 2) + r + ky) * SSTR + x0];
                float4 va = *(const float4*)rowp;
                float2 vb = *(const float2*)(rowp + 4);
                ull p0 = pack2(va.x), p1 = pack2(va.y), p2 = pack2(va.z);
                ull p3 = pack2(va.w), p4 = pack2(vb.x), p5 = pack2(vb.y);
                const ulonglong2* wp =
                    (const ulonglong2*)&sw_b[(ci * 9 + ky * 3) * 8];
#pragma unroll
                for (int kx = 0; kx < 3; kx++) {
                    ull a0 = (kx == 0) ? p0 : ((kx == 1) ? p1 : p2);
                    ull a1 = (kx == 0) ? p1 : ((kx == 1) ? p2 : p3);
                    ull a2 = (kx == 0) ? p2 : ((kx == 1) ? p3 : p4);
                    ull a3 = (kx == 0) ? p3 : ((kx == 1) ? p4 : p5);
                    ulonglong2 wa = wp[kx * 2 + 0];
                    ulonglong2 wb = wp[kx * 2 + 1];
                    ffma2(acc[0][0], a0, wa.x); ffma2(acc[0][1], a0, wa.y);
                    ffma2(acc[0][2], a0, wb.x); ffma2(acc[0][3], a0, wb.y);
                    ffma2(acc[1][0], a1, wa.x); ffma2(acc[1][1], a1, wa.y);
                    ffma2(acc[1][2], a1, wb.x); ffma2(acc[1][3], a1, wb.y);
                    ffma2(acc[2][0], a2, wa.x); ffma2(acc[2][1], a2, wa.y);
                    ffma2(acc[2][2], a2, wb.x); ffma2(acc[2][3], a2, wb.y);
                    ffma2(acc[3][0], a3, wa.x); ffma2(acc[3][1], a3, wa.y);
                    ffma2(acc[3][2], a3, wb.x); ffma2(acc[3][3], a3, wb.y);
                }
            }
        }
    };

    // ---- pipelined chunk loop: 1 barrier per chunk ----
    stage(0, 0);
    __syncthreads();
    for (int c = 0; c < NCHUNK; c++) {
        const int cur = c & 1;
        if (c + 1 < NCHUNK) stage(c + 1, cur ^ 1);
        compute(cur);
        __syncthreads();
    }

    // ---- gate math + state update (4 contiguous pixels, 2 hidden channels) ----
    const int y = gy0 + r;
#pragma unroll
    for (int hci = 0; hci < 2; hci++) {
        const int hc = hcg * 2 + hci;
        const float bi = __ldg(&bias[hc]);
        const float bf = __ldg(&bias[HIDc + hc]);
        const float bo = __ldg(&bias[2 * HIDc + hc]);
        const float bg = __ldg(&bias[3 * HIDc + hc]);
        const size_t off = ((size_t)(b * HIDc + hc) * Hdim + y) * Wdim + x0;

        float4 cp = make_float4(0.0f, 0.0f, 0.0f, 0.0f);
        if (!t0) cp = *(const float4*)(c_state + off);
        float cpv[4] = {cp.x, cp.y, cp.z, cp.w};
        float cn[4], hn[4];
#pragma unroll
        for (int xp = 0; xp < 4; xp++) {
            float2 I = unpack2(acc[xp][0]);
            float2 F = unpack2(acc[xp][1]);
            float2 O = unpack2(acc[xp][2]);
            float2 G = unpack2(acc[xp][3]);
            float iv = (hci ? I.y : I.x) + bi;
            float fv = (hci ? F.y : F.x) + bf;
            float ov = (hci ? O.y : O.x) + bo;
            float gv = (hci ? G.y : G.x) + bg;
            cn[xp] = sigm(fv) * cpv[xp] + sigm(iv) * tanh_fast(gv);
            hn[xp] = sigm(ov) * tanh_fast(cn[xp]);
        }
        *(float4*)(c_state + off) = make_float4(cn[0], cn[1], cn[2], cn[3]);
        *(float4*)(h_out + off)   = make_float4(hn[0], hn[1], hn[2], hn[3]);
    }
}

// Writes the four tail regions: h0_T, c0_T, h1_T, c1_T.
__global__ void tail_copy(float* __restrict__ out)
{
    const size_t NP = (size_t)Bn * HIDc * Hdim * Wdim;     // 1048576 floats
    size_t i4 = (size_t)blockIdx.x * blockDim.x + threadIdx.x;
    const size_t N4 = NP / 4;
    if (i4 < N4) {
        const size_t SEQ = Tn * NP;
        float4* o4 = (float4*)out;
        const float4* c0 = (const float4*)g_c0;
        const float4* c1 = (const float4*)g_c1;
        const size_t base = (2 * SEQ) / 4;
        o4[base + 0 * N4 + i4] = o4[((Tn - 1) * NP) / 4 + i4];        // h0_T
        o4[base + 1 * N4 + i4] = c0[i4];                               // c0_T
        o4[base + 2 * N4 + i4] = o4[(SEQ + (Tn - 1) * NP) / 4 + i4];   // h1_T
        o4[base + 3 * N4 + i4] = c1[i4];                               // c1_T
    }
}

extern "C" void kernel_launch(void* const* d_in, const int* in_sizes, int n_in,
                              void* d_out, int out_size)
{
    const float* x  = (const float*)d_in[0];  // [T,B,16,64,64]
    const float* W0 = (const float*)d_in[1];  // [128,48,3,3]
    const float* b0 = (const float*)d_in[2];  // [128]
    const float* W1 = (const float*)d_in[3];  // [128,64,3,3]
    const float* b1 = (const float*)d_in[4];  // [128]
    float* out = (float*)d_out;

    const size_t XS = (size_t)Bn * CINx * Hdim * Wdim;
    const size_t HS = (size_t)Bn * HIDc * Hdim * Wdim;
    float* hseq0 = out;
    float* hseq1 = out + (size_t)Tn * HS;

    dim3 grid(Hdim / TH, Bn, 16);

    for (int t = 0; t < Tn; t++) {
        const float* h0prev = t ? (hseq0 + (size_t)(t - 1) * HS) : nullptr;
        step_kernel<CINx, 0><<<grid, 256>>>(
            x + (size_t)t * XS, h0prev, W0, b0, hseq0 + (size_t)t * HS, t == 0);
        const float* h1prev = t ? (hseq1 + (size_t)(t - 1) * HS) : nullptr;
        step_kernel<HIDc, 1><<<grid, 256>>>(
            hseq0 + (size_t)t * HS, h1prev, W1, b1, hseq1 + (size_t)t * HS, t == 0);
    }
    tail_copy<<<(unsigned)((HS / 4 + 255) / 256), 256>>>(out);
}

// round 7
// speedup vs baseline: 1.2129x; 1.2129x over previous
#include <cuda_runtime.h>
#include <cuda_bf16.h>
#include <cstdint>

#define Hdim 64
#define Wdim 64
#define Bn   8
#define HIDc 32
#define Tn   16
#define CINx 16

#define CC   4          // input-channel chunk per buffer
#define TH   16         // y-rows per block (8 warps x 2 rows)
#define SSTR 68         // smem input row stride (64 + 2 halo + pad)

using ull = unsigned long long;

// Persistent cell state (device globals; NOT allocated, per harness rules).
__device__ float g_c0[(size_t)Bn * HIDc * Hdim * Wdim];
__device__ float g_c1[(size_t)Bn * HIDc * Hdim * Wdim];

__device__ __forceinline__ float sigm(float v) {
    return __fdividef(1.0f, 1.0f + __expf(-v));
}
__device__ __forceinline__ float tanh_fast(float v) {
    return 2.0f * sigm(2.0f * v) - 1.0f;
}

__device__ __forceinline__ void ffma2(ull& d, ull a, ull b) {
    asm("fma.rn.f32x2 %0, %1, %2, %0;" : "+l"(d) : "l"(a), "l"(b));
}
__device__ __forceinline__ ull pack2(float v) {
    ull r;
    asm("mov.b64 %0, {%1, %1};" : "=l"(r) : "f"(v));
    return r;
}
__device__ __forceinline__ float2 unpack2(ull v) {
    float2 f;
    asm("mov.b64 {%0, %1}, %2;" : "=f"(f.x), "=f"(f.y) : "l"(v));
    return f;
}
__device__ __forceinline__ void cp_async4(uint32_t dst_smem, const float* src) {
    asm volatile("cp.async.ca.shared.global [%0], [%1], 4;"
                 :: "r"(dst_smem), "l"(src));
}
#define CP_COMMIT() asm volatile("cp.async.commit_group;" ::: "memory")
#define CP_WAIT0()  asm volatile("cp.async.wait_group 0;" ::: "memory")

#define S_IN_CH   ((TH + 2) * SSTR)         // 18*68 = 1224 floats per channel
#define S_IN_BUF  (CC * S_IN_CH)            // 4896 floats per buffer
#define S_W_BUF   (CC * 9 * 8)              // 288 floats per buffer

// One ConvLSTM step for one layer.
// Grid: (Hdim/TH=4, Bn, 16 hidden-channel groups of 2). Block: 256 threads.
// Warp ty covers rows {2ty, 2ty+1}; lane l: sub-row l>>4, x0 = (l&15)*4.
// Each thread: 4 x-positions x (4 gates x 2 hidden channels), b64 accumulators.
// Double-buffered chunk loop with cp.async staging overlapped with compute.
template<int CIN_X, int LAYER>
__global__ __launch_bounds__(256, 4)
void step_kernel(const float* __restrict__ xsrc,   // [B, CIN_X, H, W]
                 const float* __restrict__ hsrc,   // [B, 32, H, W] (prev h) or null
                 const float* __restrict__ Wt,     // [128, CIN_X+32, 3, 3]
                 const float* __restrict__ bias,   // [128]
                 float* __restrict__ h_out,        // [B, 32, H, W]
                 int t0)
{
    constexpr int CIN_TOT = CIN_X + HIDc;            // 48 or 64
    constexpr int NCHUNK  = CIN_TOT / CC;            // 12 or 16
    __shared__ __align__(16) float s_in[2 * S_IN_BUF];   // 39168 B
    __shared__ __align__(16) float s_w[2 * S_W_BUF];     //  2304 B

    float* c_state = (LAYER == 0) ? g_c0 : g_c1;

    const int tid = threadIdx.x;
    const int l   = tid & 31;
    const int ty  = tid >> 5;
    const int sub = l >> 4;
    const int x0  = (l & 15) * 4;
    const int r   = ty * 2 + sub;        // row within tile, 0..15
    const int gy0 = blockIdx.x * TH;
    const int b   = blockIdx.y;
    const int hcg = blockIdx.z;          // hidden channels {2*hcg, 2*hcg+1}

    // Staging role: warp ty stages channel cl = ty>>1, row-half (ty&1)*9 (9 rows).
    const int st_cl = ty >> 1;
    const int st_r0 = (ty & 1) * 9;

    // ---- one-time zero fill of both buffers (covers all pads/halo/t0 rows) ----
    {
        float4* z = (float4*)s_in;
#pragma unroll
        for (int i = tid; i < (2 * S_IN_BUF) / 4; i += 256)
            z[i] = make_float4(0.f, 0.f, 0.f, 0.f);
    }

    uint32_t sin_base = (uint32_t)__cvta_generic_to_shared(s_in);
    uint32_t sw_base  = (uint32_t)__cvta_generic_to_shared(s_w);

    ull acc[4][4];
#pragma unroll
    for (int xp = 0; xp < 4; xp++)
#pragma unroll
        for (int g = 0; g < 4; g++) acc[xp][g] = 0ull;

    // ---- async staging of one chunk into buffer buf ----
    auto stage = [&](int chunk, int buf) {
        const int c = chunk * CC + st_cl;
        const float* base;
        bool valid;
        if (c < CIN_X) {
            base = xsrc + (size_t)(b * CIN_X + c) * (Hdim * Wdim);
            valid = true;
        } else {
            base = hsrc + (size_t)(b * HIDc + (c - CIN_X)) * (Hdim * Wdim);
            valid = !t0;
        }
        const uint32_t dst0 = sin_base +
            (uint32_t)(buf * S_IN_BUF + st_cl * S_IN_CH + st_r0 * SSTR) * 4u;
        if (valid) {
#pragma unroll
            for (int j = 0; j < 9; j++) {
                const int y = gy0 - 1 + st_r0 + j;
                if (y >= 0 && y < Hdim) {
                    const float* srow = base + (size_t)y * Wdim;
                    const uint32_t drow = dst0 + (uint32_t)(j * SSTR) * 4u;
                    cp_async4(drow + (1 + l) * 4u,  srow + l);        // x = l
                    cp_async4(drow + (33 + l) * 4u, srow + 32 + l);   // x = 32+l
                }
            }
        } else {
            // t0: hidden state is zero — overwrite interior with zeros.
            float* dgen = &s_in[buf * S_IN_BUF + st_cl * S_IN_CH + st_r0 * SSTR];
#pragma unroll
            for (int j = 0; j < 9; j++) {
                dgen[j * SSTR + 1 + l]  = 0.0f;
                dgen[j * SSTR + 33 + l] = 0.0f;
            }
        }
        // weights: 288 floats, layout [ci][k][8 gch], gch = gate*2 + hci
#pragma unroll
        for (int it = 0; it < 2; it++) {
            const int idx = tid + it * 256;
            if (idx < S_W_BUF) {
                const int ci  = idx / 72;
                const int rem = idx - ci * 72;
                const int k   = rem >> 3;
                const int gi  = rem & 7;
                const int oc  = (gi >> 1) * HIDc + hcg * 2 + (gi & 1);
                cp_async4(sw_base + (uint32_t)(buf * S_W_BUF + idx) * 4u,
                          Wt + ((size_t)oc * CIN_TOT + (chunk * CC + ci)) * 9 + k);
            }
        }
        CP_COMMIT();
    };

    auto compute = [&](int buf) {
        const float* sin_b = &s_in[buf * S_IN_BUF];
        const float* sw_b  = &s_w[buf * S_W_BUF];
#pragma unroll
        for (int ci = 0; ci < CC; ci++) {
#pragma unroll
            for (int ky = 0; ky < 3; ky++) {
                const float* rowp = &sin_b[(ci * (TH + 2) + r + ky) * SSTR + x0];
                float4 va = *(const float4*)rowp;
                float2 vb = *(const float2*)(rowp + 4);
                ull p0 = pack2(va.x), p1 = pack2(va.y), p2 = pack2(va.z);
                ull p3 = pack2(va.w), p4 = pack2(vb.x), p5 = pack2(vb.y);
                const ulonglong2* wp =
                    (const ulonglong2*)&sw_b[(ci * 9 + ky * 3) * 8];
#pragma unroll
                for (int kx = 0; kx < 3; kx++) {
                    ull a0 = (kx == 0) ? p0 : ((kx == 1) ? p1 : p2);
                    ull a1 = (kx == 0) ? p1 : ((kx == 1) ? p2 : p3);
                    ull a2 = (kx == 0) ? p2 : ((kx == 1) ? p3 : p4);
                    ull a3 = (kx == 0) ? p3 : ((kx == 1) ? p4 : p5);
                    ulonglong2 wa = wp[kx * 2 + 0];
                    ulonglong2 wb = wp[kx * 2 + 1];
                    ffma2(acc[0][0], a0, wa.x); ffma2(acc[0][1], a0, wa.y);
                    ffma2(acc[0][2], a0, wb.x); ffma2(acc[0][3], a0, wb.y);
                    ffma2(acc[1][0], a1, wa.x); ffma2(acc[1][1], a1, wa.y);
                    ffma2(acc[1][2], a1, wb.x); ffma2(acc[1][3], a1, wb.y);
                    ffma2(acc[2][0], a2, wa.x); ffma2(acc[2][1], a2, wa.y);
                    ffma2(acc[2][2], a2, wb.x); ffma2(acc[2][3], a2, wb.y);
                    ffma2(acc[3][0], a3, wa.x); ffma2(acc[3][1], a3, wa.y);
                    ffma2(acc[3][2], a3, wb.x); ffma2(acc[3][3], a3, wb.y);
                }
            }
        }
    };

    // Zero-fill must be visible before first cp.async writes interleave.
    __syncthreads();

    // ---- pipelined chunk loop: stage(c+1) overlaps compute(c) ----
    stage(0, 0);
    for (int c = 0; c < NCHUNK; c++) {
        const int cur = c & 1;
        CP_WAIT0();          // my cp.asyncs for chunk c are done
        __syncthreads();     // everyone's are done; prev compute finished
        if (c + 1 < NCHUNK) stage(c + 1, cur ^ 1);
        compute(cur);
    }

    // ---- gate math + state update (4 contiguous pixels, 2 hidden channels) ----
    const int y = gy0 + r;
#pragma unroll
    for (int hci = 0; hci < 2; hci++) {
        const int hc = hcg * 2 + hci;
        const float bi = __ldg(&bias[hc]);
        const float bf = __ldg(&bias[HIDc + hc]);
        const float bo = __ldg(&bias[2 * HIDc + hc]);
        const float bg = __ldg(&bias[3 * HIDc + hc]);
        const size_t off = ((size_t)(b * HIDc + hc) * Hdim + y) * Wdim + x0;

        float4 cp = make_float4(0.0f, 0.0f, 0.0f, 0.0f);
        if (!t0) cp = *(const float4*)(c_state + off);
        float cpv[4] = {cp.x, cp.y, cp.z, cp.w};
        float cn[4], hn[4];
#pragma unroll
        for (int xp = 0; xp < 4; xp++) {
            float2 I = unpack2(acc[xp][0]);
            float2 F = unpack2(acc[xp][1]);
            float2 O = unpack2(acc[xp][2]);
            float2 G = unpack2(acc[xp][3]);
            float iv = (hci ? I.y : I.x) + bi;
            float fv = (hci ? F.y : F.x) + bf;
            float ov = (hci ? O.y : O.x) + bo;
            float gv = (hci ? G.y : G.x) + bg;
            cn[xp] = sigm(fv) * cpv[xp] + sigm(iv) * tanh_fast(gv);
            hn[xp] = sigm(ov) * tanh_fast(cn[xp]);
        }
        *(float4*)(c_state + off) = make_float4(cn[0], cn[1], cn[2], cn[3]);
        *(float4*)(h_out + off)   = make_float4(hn[0], hn[1], hn[2], hn[3]);
    }
}

// Writes the four tail regions: h0_T, c0_T, h1_T, c1_T.
__global__ void tail_copy(float* __restrict__ out)
{
    const size_t NP = (size_t)Bn * HIDc * Hdim * Wdim;     // 1048576 floats
    size_t i4 = (size_t)blockIdx.x * blockDim.x + threadIdx.x;
    const size_t N4 = NP / 4;
    if (i4 < N4) {
        const size_t SEQ = Tn * NP;
        float4* o4 = (float4*)out;
        const float4* c0 = (const float4*)g_c0;
        const float4* c1 = (const float4*)g_c1;
        const size_t base = (2 * SEQ) / 4;
        o4[base + 0 * N4 + i4] = o4[((Tn - 1) * NP) / 4 + i4];        // h0_T
        o4[base + 1 * N4 + i4] = c0[i4];                               // c0_T
        o4[base + 2 * N4 + i4] = o4[(SEQ + (Tn - 1) * NP) / 4 + i4];   // h1_T
        o4[base + 3 * N4 + i4] = c1[i4];                               // c1_T
    }
}

extern "C" void kernel_launch(void* const* d_in, const int* in_sizes, int n_in,
                              void* d_out, int out_size)
{
    const float* x  = (const float*)d_in[0];  // [T,B,16,64,64]
    const float* W0 = (const float*)d_in[1];  // [128,48,3,3]
    const float* b0 = (const float*)d_in[2];  // [128]
    const float* W1 = (const float*)d_in[3];  // [128,64,3,3]
    const float* b1 = (const float*)d_in[4];  // [128]
    float* out = (float*)d_out;

    const size_t XS = (size_t)Bn * CINx * Hdim * Wdim;
    const size_t HS = (size_t)Bn * HIDc * Hdim * Wdim;
    float* hseq0 = out;
    float* hseq1 = out + (size_t)Tn * HS;

    dim3 grid(Hdim / TH, Bn, 16);

    for (int t = 0; t < Tn; t++) {
        const float* h0prev = t ? (hseq0 + (size_t)(t - 1) * HS) : hseq0;
        step_kernel<CINx, 0><<<grid, 256>>>(
            x + (size_t)t * XS, h0prev, W0, b0, hseq0 + (size_t)t * HS, t == 0);
        const float* h1prev = t ? (hseq1 + (size_t)(t - 1) * HS) : hseq1;
        step_kernel<HIDc, 1><<<grid, 256>>>(
            hseq0 + (size_t)t * HS, h1prev, W1, b1, hseq1 + (size_t)t * HS, t == 0);
    }
    tail_copy<<<(unsigned)((HS / 4 + 255) / 256), 256>>>(out);
}